// round 2
// baseline (speedup 1.0000x reference)
#include <cuda_runtime.h>
#include <cuda_bf16.h>
#include <cstdint>

#define DD 512
#define MAXN 200000
#define TAU_INV 2.0f
#define EPS 1e-8f

// ---------------- device scratch (no allocations allowed) ----------------
__device__ __nv_bfloat16 g_zbf[(size_t)MAXN * DD];   // z in bf16
__device__ __nv_bfloat16 g_wbf[DD * DD];             // W in bf16
__device__ float g_d2[MAXN];
__device__ float g_colsum[DD];
__device__ float g_c0[DD];                           // init centroid
__device__ float g_c[DD];                            // softmax centroid
__device__ float g_v[DD];                            // v = W^T c
__device__ float g_Z;                                // softmax partition
__device__ float g_bc;                               // b . c
__device__ float g_cnorm;                            // max(||c||, eps)
__device__ int   g_d2min_bits;

// ---------------- helpers ----------------
__device__ __forceinline__ uint32_t smem_u32(const void* p) {
    return (uint32_t)__cvta_generic_to_shared(p);
}
__device__ __forceinline__ void ldmx4(uint32_t* r, uint32_t addr) {
    asm volatile("ldmatrix.sync.aligned.m8n8.x4.shared.b16 {%0,%1,%2,%3}, [%4];"
                 : "=r"(r[0]), "=r"(r[1]), "=r"(r[2]), "=r"(r[3]) : "r"(addr));
}
__device__ __forceinline__ void mma16816(float* c, const uint32_t* a, const uint32_t* b) {
    asm volatile("mma.sync.aligned.m16n8k16.row.col.f32.bf16.bf16.f32 "
                 "{%0,%1,%2,%3}, {%4,%5,%6,%7}, {%8,%9}, {%0,%1,%2,%3};"
                 : "+f"(c[0]), "+f"(c[1]), "+f"(c[2]), "+f"(c[3])
                 : "r"(a[0]), "r"(a[1]), "r"(a[2]), "r"(a[3]), "r"(b[0]), "r"(b[1]));
}

// ================= k0: init scratch + W -> bf16 =================
__global__ void k0_init(const float* __restrict__ W) {
    int i = blockIdx.x * blockDim.x + threadIdx.x;
    int stride = gridDim.x * blockDim.x;
    for (int j = i; j < DD * DD; j += stride) g_wbf[j] = __float2bfloat16(W[j]);
    if (i < DD) { g_colsum[i] = 0.f; g_c[i] = 0.f; g_v[i] = 0.f; }
    if (i == 0) { g_Z = 0.f; g_d2min_bits = 0x7f7fffff; }
}

// ================= k1: colsums + z->bf16 =================
__global__ void k1_pass1(const float* __restrict__ z, int N) {
    __shared__ float scol[DD];
    const int tid = threadIdx.x, wid = tid >> 5, lane = tid & 31;
    for (int i = tid; i < DD; i += blockDim.x) scol[i] = 0.f;
    __syncthreads();
    const int gw = blockIdx.x * (blockDim.x >> 5) + wid;
    const int nw = gridDim.x * (blockDim.x >> 5);
    float cs[16];
#pragma unroll
    for (int i = 0; i < 16; i++) cs[i] = 0.f;
    for (int row = gw; row < N; row += nw) {
        const float4* zr = (const float4*)(z + (size_t)row * DD);
#pragma unroll
        for (int c = 0; c < 4; c++) {
            float4 v = zr[c * 32 + lane];
            cs[c * 4 + 0] += v.x; cs[c * 4 + 1] += v.y;
            cs[c * 4 + 2] += v.z; cs[c * 4 + 3] += v.w;
            __nv_bfloat162 b0 = __floats2bfloat162_rn(v.x, v.y);
            __nv_bfloat162 b1 = __floats2bfloat162_rn(v.z, v.w);
            uint2 u;
            u.x = *reinterpret_cast<uint32_t*>(&b0);
            u.y = *reinterpret_cast<uint32_t*>(&b1);
            *(uint2*)(g_zbf + (size_t)row * DD + c * 128 + lane * 4) = u;
        }
    }
#pragma unroll
    for (int c = 0; c < 4; c++)
#pragma unroll
        for (int e = 0; e < 4; e++)
            atomicAdd(&scol[c * 128 + lane * 4 + e], cs[c * 4 + e]);
    __syncthreads();
    for (int i = tid; i < DD; i += blockDim.x) atomicAdd(&g_colsum[i], scol[i]);
}

// ================= k2: c0 = colsum/N =================
__global__ void k2_c0(int N) {
    const int tid = threadIdx.x; // 512 threads
    g_c0[tid] = g_colsum[tid] / (float)N;
}

// ================= k3: d2 = ||h - c0||^2 (fp32, direct) =================
__global__ void k3_d2(const float* __restrict__ z, int N) {
    __shared__ __align__(16) float c0s[DD];
    const int tid = threadIdx.x, wid = tid >> 5, lane = tid & 31;
    for (int i = tid; i < DD; i += blockDim.x) c0s[i] = g_c0[i];
    __syncthreads();
    const int gw = blockIdx.x * (blockDim.x >> 5) + wid;
    const int nw = gridDim.x * (blockDim.x >> 5);
    for (int row = gw; row < N; row += nw) {
        const float4* zr = (const float4*)(z + (size_t)row * DD);
        float acc = 0.f;
#pragma unroll
        for (int c = 0; c < 4; c++) {
            float4 v = zr[c * 32 + lane];
            float4 cv = ((const float4*)c0s)[c * 32 + lane];
            float dx = v.x - cv.x, dy = v.y - cv.y, dz = v.z - cv.z, dw = v.w - cv.w;
            acc += dx * dx + dy * dy + dz * dz + dw * dw;
        }
#pragma unroll
        for (int o = 16; o > 0; o >>= 1) acc += __shfl_xor_sync(0xffffffffu, acc, o);
        if (lane == 0) {
            g_d2[row] = acc;
            atomicMin(&g_d2min_bits, __float_as_int(acc)); // d2 >= 0
        }
    }
}

// ================= k4: Z = sum exp(-(d2-d2min)*2) =================
__global__ void k4_Z(int N) {
    __shared__ float red[8];
    const int tid = threadIdx.x;
    const float d2min = __int_as_float(g_d2min_bits);
    float s = 0.f;
    for (int r = blockIdx.x * blockDim.x + tid; r < N; r += gridDim.x * blockDim.x)
        s += expf((d2min - g_d2[r]) * TAU_INV);
#pragma unroll
    for (int o = 16; o > 0; o >>= 1) s += __shfl_xor_sync(0xffffffffu, s, o);
    if ((tid & 31) == 0) red[tid >> 5] = s;
    __syncthreads();
    if (tid < 8) {
        float t = red[tid];
#pragma unroll
        for (int o = 4; o > 0; o >>= 1) t += __shfl_xor_sync(0xffu, t, o);
        if (tid == 0) atomicAdd(&g_Z, t);
    }
}

// ================= k5: c = sum w_i h_i (fp32 z, skip negligible w) =================
__global__ void k5_c(const float* __restrict__ z, int N) {
    const int tid = threadIdx.x, wid = tid >> 5, lane = tid & 31;
    const float d2min = __int_as_float(g_d2min_bits);
    const float invZ = 1.f / g_Z;
    const int gw = blockIdx.x * (blockDim.x >> 5) + wid;
    const int nw = gridDim.x * (blockDim.x >> 5);
    for (int row = gw; row < N; row += nw) {
        float w = expf((d2min - g_d2[row]) * TAU_INV) * invZ;
        if (w < 1e-12f) continue;
        const float4* zr = (const float4*)(z + (size_t)row * DD);
#pragma unroll
        for (int c = 0; c < 4; c++) {
            float4 v = zr[c * 32 + lane];
            int base = c * 128 + lane * 4;
            atomicAdd(&g_c[base + 0], w * v.x);
            atomicAdd(&g_c[base + 1], w * v.y);
            atomicAdd(&g_c[base + 2], w * v.z);
            atomicAdd(&g_c[base + 3], w * v.w);
        }
    }
}

// ================= k6: v = W^T c (fp32 exact) =================
__global__ void k6_v(const float* __restrict__ W) {
    __shared__ float cs[16];
    const int tid = threadIdx.x; // 512 threads
    const int j0 = blockIdx.x * 16;
    if (tid < 16) cs[tid] = g_c[j0 + tid];
    __syncthreads();
    float acc = 0.f;
#pragma unroll
    for (int jj = 0; jj < 16; jj++)
        acc += cs[jj] * W[(size_t)(j0 + jj) * DD + tid];
    atomicAdd(&g_v[tid], acc);
}

// ================= k7: bc = b.c, cnorm = max(||c||,eps) =================
__global__ void k7_scalars(const float* __restrict__ b) {
    __shared__ float redb[16], redc[16];
    const int tid = threadIdx.x; // 512 threads
    float cv = g_c[tid];
    float pb = cv * b[tid];
    float pc = cv * cv;
#pragma unroll
    for (int o = 16; o > 0; o >>= 1) {
        pb += __shfl_xor_sync(0xffffffffu, pb, o);
        pc += __shfl_xor_sync(0xffffffffu, pc, o);
    }
    if ((tid & 31) == 0) { redb[tid >> 5] = pb; redc[tid >> 5] = pc; }
    __syncthreads();
    if (tid < 16) {
        float sb = redb[tid], sc = redc[tid];
#pragma unroll
        for (int o = 8; o > 0; o >>= 1) {
            sb += __shfl_xor_sync(0xffffu, sb, o);
            sc += __shfl_xor_sync(0xffffu, sc, o);
        }
        if (tid == 0) { g_bc = sb; g_cnorm = fmaxf(sqrtf(sc), EPS); }
    }
}

// ================= k8: mma.sync GEMM + fused norm/dot/dist =================
// SMEM layout (bytes):
//   A tile : [0, 131072)          128 rows x 512 bf16, swizzled
//   B tile : [131072, 196608)     64 j-rows x 512 bf16, swizzled
//   v      : [196608, 198656)     512 f32
//   b      : [198656, 200704)     512 f32
//   nsq    : [200704, 201216)     128 f32
#define K8_A    0
#define K8_B    131072
#define K8_V    196608
#define K8_BV   198656
#define K8_NSQ  200704
#define K8_SMEM 201728

__global__ void __launch_bounds__(256, 1)
k8_gemm(const float* __restrict__ b_in, float* __restrict__ out, int N) {
    extern __shared__ char smem[];
    const uint32_t sbase = smem_u32(smem);
    const int tid = threadIdx.x, warp = tid >> 5, lane = tid & 31;
    const int m0 = blockIdx.x * 128;

    float* sv  = (float*)(smem + K8_V);
    float* sbv = (float*)(smem + K8_BV);
    float* snq = (float*)(smem + K8_NSQ);

    for (int i = tid; i < DD; i += 256) { sv[i] = g_v[i]; sbv[i] = b_in[i]; }
    if (tid < 128) snq[tid] = 0.f;

    // ---- load A: 128 rows x 512 bf16, chunk-XOR swizzle (16B chunks) ----
#pragma unroll
    for (int it = 0; it < 32; it++) {
        int idx = it * 256 + tid;
        int r = idx >> 6, ci = idx & 63;
        int grow = m0 + r; if (grow > N - 1) grow = N - 1;
        uint4 val = *(const uint4*)(g_zbf + (size_t)grow * DD + ci * 8);
        *(uint4*)(smem + K8_A + r * 1024 + ((ci ^ (r & 7)) << 4)) = val;
    }
    __syncthreads();

    // ---- dot z.v from A SMEM: thread r (<128) owns row r ----
    float dacc = 0.f;
    if (tid < 128) {
        const int sw = tid & 7;
        const char* rowp = smem + K8_A + tid * 1024;
#pragma unroll 8
        for (int ci = 0; ci < 64; ci++) {
            uint4 u = *(const uint4*)(rowp + ((ci ^ sw) << 4));
            const __nv_bfloat162* p = (const __nv_bfloat162*)&u;
            const float* vv = sv + ci * 8;
#pragma unroll
            for (int q = 0; q < 4; q++) {
                float2 f = __bfloat1622float2(p[q]);
                dacc += f.x * vv[q * 2] + f.y * vv[q * 2 + 1];
            }
        }
    }

    // ---- warp tiling: 4 m-groups x 2 j-groups, warp tile m32 x j32 ----
    const int mg = warp & 3, jg = warp >> 2;
    const int mbase = mg * 32;
    const uint32_t swa = lane & 7;
    const uint32_t a0base = sbase + K8_A + (uint32_t)(mbase + (lane & 15)) * 1024;
    const int jrow = (lane & 7) + ((lane >> 4) << 3);
    const uint32_t b0base = sbase + K8_B + (uint32_t)(jg * 32 + jrow) * 1024;
    const uint32_t ciBofs = (lane >> 3) & 1;
    const uint32_t ciAofs = lane >> 4;

    float nsq[2][2];
    nsq[0][0] = nsq[0][1] = nsq[1][0] = nsq[1][1] = 0.f;

    for (int jc = 0; jc < 8; jc++) {
        __syncthreads();   // previous chunk's B fully consumed
        // ---- load B chunk: W rows jc*64 .. +64, all k ----
#pragma unroll
        for (int it = 0; it < 16; it++) {
            int idx = it * 256 + tid;
            int j = idx >> 6, ci = idx & 63;
            uint4 val = *(const uint4*)(g_wbf + (size_t)(jc * 64 + j) * DD + ci * 8);
            *(uint4*)(smem + K8_B + j * 1024 + ((ci ^ (j & 7)) << 4)) = val;
        }
        __syncthreads();

        float acc[8][4];
#pragma unroll
        for (int t = 0; t < 8; t++)
#pragma unroll
            for (int e = 0; e < 4; e++) acc[t][e] = 0.f;

#pragma unroll 4
        for (int kt = 0; kt < 32; kt++) {
            uint32_t a0[4], a1[4], b0[4], b1[4];
            uint32_t ciA = (uint32_t)kt * 2 + ciAofs;
            uint32_t adr = a0base + ((ciA ^ swa) << 4);
            ldmx4(a0, adr);
            ldmx4(a1, adr + 16 * 1024);
            uint32_t ciB = (uint32_t)kt * 2 + ciBofs;
            uint32_t bdr = b0base + ((ciB ^ swa) << 4);
            ldmx4(b0, bdr);
            ldmx4(b1, bdr + 16 * 1024);
            mma16816(acc[0], a0, b0 + 0);
            mma16816(acc[1], a0, b0 + 2);
            mma16816(acc[2], a0, b1 + 0);
            mma16816(acc[3], a0, b1 + 2);
            mma16816(acc[4], a1, b0 + 0);
            mma16816(acc[5], a1, b0 + 2);
            mma16816(acc[6], a1, b1 + 0);
            mma16816(acc[7], a1, b1 + 2);
        }

        // ---- fold (acc + b[j])^2 into per-row norm partials ----
#pragma unroll
        for (int mt = 0; mt < 2; mt++)
#pragma unroll
            for (int nt = 0; nt < 4; nt++) {
                int jglob = jc * 64 + jg * 32 + nt * 8 + (lane & 3) * 2;
                float bx = sbv[jglob], by = sbv[jglob + 1];
                float* a = acc[mt * 4 + nt];
                float v0 = a[0] + bx, v1 = a[1] + by;
                float v2 = a[2] + bx, v3 = a[3] + by;
                nsq[mt][0] += v0 * v0 + v1 * v1;
                nsq[mt][1] += v2 * v2 + v3 * v3;
            }
    }

    // ---- merge lane partials: quad lanes share a row ----
#pragma unroll
    for (int mt = 0; mt < 2; mt++)
#pragma unroll
        for (int h = 0; h < 2; h++) {
            float v = nsq[mt][h];
            v += __shfl_xor_sync(0xffffffffu, v, 1);
            v += __shfl_xor_sync(0xffffffffu, v, 2);
            if ((lane & 3) == 0)
                atomicAdd(&snq[mbase + mt * 16 + h * 8 + (lane >> 2)], v);
        }
    __syncthreads();

    if (tid < 128 && m0 + tid < N) {
        float nx = fmaxf(sqrtf(snq[tid]), EPS);
        out[m0 + tid] = 1.0f - (dacc + g_bc) / (nx * g_cnorm);
    }
}

// ================= launch =================
extern "C" void kernel_launch(void* const* d_in, const int* in_sizes, int n_in,
                              void* d_out, int out_size) {
    const float* z = (const float*)d_in[0];
    const float* W = (const float*)d_in[1];
    const float* b = (const float*)d_in[2];
    float* out = (float*)d_out;
    const int N = in_sizes[0] / DD;

    k0_init<<<1024, 256>>>(W);
    k1_pass1<<<1184, 256>>>(z, N);
    k2_c0<<<1, 512>>>(N);
    k3_d2<<<1184, 256>>>(z, N);
    k4_Z<<<256, 256>>>(N);
    k5_c<<<1184, 256>>>(z, N);
    k6_v<<<32, 512>>>(W);
    k7_scalars<<<1, 512>>>(b);
    cudaFuncSetAttribute(k8_gemm, cudaFuncAttributeMaxDynamicSharedMemorySize, K8_SMEM);
    k8_gemm<<<(N + 127) / 128, 256, K8_SMEM>>>(b, out, N);
}

// round 4
// speedup vs baseline: 1.3566x; 1.3566x over previous
#include <cuda_runtime.h>
#include <cuda_bf16.h>
#include <cstdint>

#define DD 512
#define MAXN 200000
#define TAU_INV 2.0f
#define EPS 1e-8f

// ---------------- device scratch (no allocations allowed) ----------------
__device__ __nv_bfloat16 g_zbf[(size_t)MAXN * DD];   // z in bf16
__device__ __nv_bfloat16 g_wbf[DD * DD];             // W in bf16
__device__ float g_s[MAXN];                          // row sumsq of z (fp32)
__device__ float g_d2[MAXN];
__device__ float g_colsum[DD];
__device__ float g_c0[DD];                           // init centroid
__device__ float g_cp[DD];                           // unnormalized softmax centroid
__device__ float g_c[DD];                            // normalized centroid
__device__ float g_cc;                               // ||c0||^2
__device__ float g_Z;                                // softmax partition
__device__ float g_cnorm;                            // max(||c||, eps)
__device__ int   g_d2min_bits;

// ---------------- helpers ----------------
__device__ __forceinline__ uint32_t smem_u32(const void* p) {
    return (uint32_t)__cvta_generic_to_shared(p);
}
__device__ __forceinline__ void ldmx4(uint32_t* r, uint32_t addr) {
    asm volatile("ldmatrix.sync.aligned.m8n8.x4.shared.b16 {%0,%1,%2,%3}, [%4];"
                 : "=r"(r[0]), "=r"(r[1]), "=r"(r[2]), "=r"(r[3]) : "r"(addr));
}
__device__ __forceinline__ void mma16816(float* c, const uint32_t* a, const uint32_t* b) {
    asm volatile("mma.sync.aligned.m16n8k16.row.col.f32.bf16.bf16.f32 "
                 "{%0,%1,%2,%3}, {%4,%5,%6,%7}, {%8,%9}, {%0,%1,%2,%3};"
                 : "+f"(c[0]), "+f"(c[1]), "+f"(c[2]), "+f"(c[3])
                 : "r"(a[0]), "r"(a[1]), "r"(a[2]), "r"(a[3]), "r"(b[0]), "r"(b[1]));
}
__device__ __forceinline__ void cp_async16(uint32_t sdst, const void* gsrc) {
    asm volatile("cp.async.cg.shared.global [%0], [%1], 16;"
                 :: "r"(sdst), "l"(gsrc) : "memory");
}
__device__ __forceinline__ void cp_commit() {
    asm volatile("cp.async.commit_group;" ::: "memory");
}
__device__ __forceinline__ void cp_wait1() {
    asm volatile("cp.async.wait_group 1;" ::: "memory");
}

// ================= k0: init scratch + W -> bf16 =================
__global__ void k0_init(const float* __restrict__ W) {
    int i = blockIdx.x * blockDim.x + threadIdx.x;
    int stride = gridDim.x * blockDim.x;
    for (int j = i; j < DD * DD; j += stride) g_wbf[j] = __float2bfloat16(W[j]);
    if (i < DD) { g_colsum[i] = 0.f; g_cp[i] = 0.f; }
    if (i == 0) { g_Z = 0.f; g_d2min_bits = 0x7f7fffff; }
}

// ================= k1: colsums + row sumsq + z->bf16 =================
__global__ void k1_pass1(const float* __restrict__ z, int N) {
    __shared__ float scol[DD];
    const int tid = threadIdx.x, wid = tid >> 5, lane = tid & 31;
    for (int i = tid; i < DD; i += blockDim.x) scol[i] = 0.f;
    __syncthreads();
    const int gw = blockIdx.x * (blockDim.x >> 5) + wid;
    const int nw = gridDim.x * (blockDim.x >> 5);
    float cs[16];
#pragma unroll
    for (int i = 0; i < 16; i++) cs[i] = 0.f;
    for (int row = gw; row < N; row += nw) {
        const float4* zr = (const float4*)(z + (size_t)row * DD);
        float ssq = 0.f;
#pragma unroll
        for (int c = 0; c < 4; c++) {
            float4 v = zr[c * 32 + lane];
            ssq += v.x * v.x + v.y * v.y + v.z * v.z + v.w * v.w;
            cs[c * 4 + 0] += v.x; cs[c * 4 + 1] += v.y;
            cs[c * 4 + 2] += v.z; cs[c * 4 + 3] += v.w;
            __nv_bfloat162 b0 = __floats2bfloat162_rn(v.x, v.y);
            __nv_bfloat162 b1 = __floats2bfloat162_rn(v.z, v.w);
            uint2 u;
            u.x = *reinterpret_cast<uint32_t*>(&b0);
            u.y = *reinterpret_cast<uint32_t*>(&b1);
            *(uint2*)(g_zbf + (size_t)row * DD + c * 128 + lane * 4) = u;
        }
#pragma unroll
        for (int o = 16; o > 0; o >>= 1) ssq += __shfl_xor_sync(0xffffffffu, ssq, o);
        if (lane == 0) g_s[row] = ssq;
    }
#pragma unroll
    for (int c = 0; c < 4; c++)
#pragma unroll
        for (int e = 0; e < 4; e++)
            atomicAdd(&scol[c * 128 + lane * 4 + e], cs[c * 4 + e]);
    __syncthreads();
    for (int i = tid; i < DD; i += blockDim.x) atomicAdd(&g_colsum[i], scol[i]);
}

// ================= k2: c0 = colsum/N, cc = ||c0||^2 =================
__global__ void k2_c0(int N) {
    __shared__ float red[16];
    const int tid = threadIdx.x; // 512
    float c0 = g_colsum[tid] / (float)N;
    g_c0[tid] = c0;
    float sq = c0 * c0;
#pragma unroll
    for (int o = 16; o > 0; o >>= 1) sq += __shfl_xor_sync(0xffffffffu, sq, o);
    if ((tid & 31) == 0) red[tid >> 5] = sq;
    __syncthreads();
    if (tid < 16) {
        float s = red[tid];
#pragma unroll
        for (int o = 8; o > 0; o >>= 1) s += __shfl_xor_sync(0xffffu, s, o);
        if (tid == 0) g_cc = s;
    }
}

// ================= k3: d2 = s - 2 h.c0 + cc (bf16 h), block-min =================
__global__ void k3_d2(int N) {
    __shared__ __align__(16) float c0s[DD];
    __shared__ int smin;
    const int tid = threadIdx.x, wid = tid >> 5, lane = tid & 31;
    for (int i = tid; i < DD; i += blockDim.x) c0s[i] = g_c0[i];
    if (tid == 0) smin = 0x7f7fffff;
    __syncthreads();
    const float cc = g_cc;
    const int gw = blockIdx.x * (blockDim.x >> 5) + wid;
    const int nw = gridDim.x * (blockDim.x >> 5);
    for (int r4 = gw * 4; r4 < N; r4 += nw * 4) {
        float t[4] = {0.f, 0.f, 0.f, 0.f};
        int nr = (N - r4 < 4) ? (N - r4) : 4;
#pragma unroll
        for (int q = 0; q < 4; q++) {
            int row = r4 + ((q < nr) ? q : 0);
#pragma unroll
            for (int c = 0; c < 2; c++) {
                uint4 u = *(const uint4*)(g_zbf + (size_t)row * DD + c * 256 + lane * 8);
                const __nv_bfloat162* p = (const __nv_bfloat162*)&u;
                float4 cv0 = ((const float4*)c0s)[c * 64 + lane * 2];
                float4 cv1 = ((const float4*)c0s)[c * 64 + lane * 2 + 1];
                float2 f0 = __bfloat1622float2(p[0]);
                float2 f1 = __bfloat1622float2(p[1]);
                float2 f2 = __bfloat1622float2(p[2]);
                float2 f3 = __bfloat1622float2(p[3]);
                t[q] += f0.x * cv0.x + f0.y * cv0.y + f1.x * cv0.z + f1.y * cv0.w
                      + f2.x * cv1.x + f2.y * cv1.y + f3.x * cv1.z + f3.y * cv1.w;
            }
        }
#pragma unroll
        for (int q = 0; q < 4; q++)
#pragma unroll
            for (int o = 16; o > 0; o >>= 1)
                t[q] += __shfl_xor_sync(0xffffffffu, t[q], o);
        if (lane == 0) {
            int lmin = 0x7f7fffff;
#pragma unroll
            for (int q = 0; q < 4; q++) {
                if (q < nr) {
                    float d2 = g_s[r4 + q] - 2.f * t[q] + cc;
                    g_d2[r4 + q] = d2;
                    int bits = __float_as_int(d2);
                    if (bits < lmin) lmin = bits;
                }
            }
            atomicMin(&smin, lmin);
        }
    }
    __syncthreads();
    if (tid == 0) atomicMin(&g_d2min_bits, smin);
}

// ================= k45: Z + unnormalized centroid c' (uniform trip count) ====
__global__ void k45_Zc(const float* __restrict__ z, int N) {
    __shared__ float red[8];
    const int tid = threadIdx.x, lane = tid & 31;
    const float d2min = __int_as_float(g_d2min_bits);
    const int gidx = blockIdx.x * blockDim.x + tid;
    const int stride = gridDim.x * blockDim.x;
    const int numIter = (N + stride - 1) / stride;   // identical for all threads
    float zpart = 0.f;
    for (int i = 0; i < numIter; i++) {
        int r = gidx + i * stride;
        float e = 0.f;
        if (r < N) e = __expf((d2min - g_d2[r]) * TAU_INV);
        zpart += e;
        unsigned mask = __ballot_sync(0xffffffffu, e > 1e-13f);
        while (mask) {
            int src = __ffs(mask) - 1;
            mask &= mask - 1;
            int rb = __shfl_sync(0xffffffffu, r, src);
            float eb = __shfl_sync(0xffffffffu, e, src);
            const float* zr = z + (size_t)rb * DD;
#pragma unroll
            for (int c = 0; c < 16; c++)
                atomicAdd(&g_cp[c * 32 + lane], eb * zr[c * 32 + lane]);
        }
    }
#pragma unroll
    for (int o = 16; o > 0; o >>= 1) zpart += __shfl_xor_sync(0xffffffffu, zpart, o);
    if (lane == 0) red[tid >> 5] = zpart;
    __syncthreads();
    if (tid < 8) {
        float t = red[tid];
#pragma unroll
        for (int o = 4; o > 0; o >>= 1) t += __shfl_xor_sync(0xffu, t, o);
        if (tid == 0) atomicAdd(&g_Z, t);
    }
}

// ================= k7: c = c'/Z, cnorm =================
__global__ void k7_norm() {
    __shared__ float red[16];
    const int tid = threadIdx.x; // 512
    const float invZ = 1.f / g_Z;
    float cv = g_cp[tid] * invZ;
    g_c[tid] = cv;
    float pc = cv * cv;
#pragma unroll
    for (int o = 16; o > 0; o >>= 1) pc += __shfl_xor_sync(0xffffffffu, pc, o);
    if ((tid & 31) == 0) red[tid >> 5] = pc;
    __syncthreads();
    if (tid < 16) {
        float sc = red[tid];
#pragma unroll
        for (int o = 8; o > 0; o >>= 1) sc += __shfl_xor_sync(0xffffu, sc, o);
        if (tid == 0) g_cnorm = fmaxf(sqrtf(sc), EPS);
    }
}

// ================= k8: mma.sync GEMM, cp.async-pipelined B, fused epilogue ====
// SMEM (bytes):
//   A    : [0, 131072)           128 rows x 512 bf16, pitch 1024, XOR swizzle
//   B    : [131072, +2x32768)    2 half-buffers, 64 j x 256 k bf16, pitch 512
//   c    : [196608, 198656)      512 f32
//   b    : [198656, 200704)      512 f32
//   nsq  : [200704, 201216)      128 f32
//   cos  : [201216, 201728)      128 f32
#define K8_A    0
#define K8_B    131072
#define K8_BHB  32768
#define K8_C    196608
#define K8_BV   198656
#define K8_NSQ  200704
#define K8_COS  201216
#define K8_SMEM 201728

__global__ void __launch_bounds__(256, 1)
k8_gemm(const float* __restrict__ b_in, float* __restrict__ out, int N) {
    extern __shared__ char smem[];
    const uint32_t sbase = smem_u32(smem);
    const int tid = threadIdx.x, warp = tid >> 5, lane = tid & 31;
    const int m0 = blockIdx.x * 128;

    float* sc  = (float*)(smem + K8_C);
    float* sbv = (float*)(smem + K8_BV);
    float* snq = (float*)(smem + K8_NSQ);
    float* sco = (float*)(smem + K8_COS);

    for (int i = tid; i < DD; i += 256) { sc[i] = g_c[i]; sbv[i] = b_in[i]; }
    if (tid < 128) { snq[tid] = 0.f; sco[tid] = 0.f; }

    // ---- prefetch B halves 0 and 1 via cp.async ----
#pragma unroll 1
    for (int h = 0; h < 2; h++) {
        const uint32_t bbuf = sbase + K8_B + (h & 1) * K8_BHB;
        const int jc = h >> 1, kh = h & 1;
#pragma unroll
        for (int it = 0; it < 8; it++) {
            int idx = it * 256 + tid;
            int j = idx >> 5, ci = idx & 31;
            cp_async16(bbuf + j * 512 + ((ci ^ (j & 7)) << 4),
                       g_wbf + (size_t)(jc * 64 + j) * DD + kh * 256 + ci * 8);
        }
        cp_commit();
    }

    // ---- load A: 128 rows x 512 bf16 ----
#pragma unroll
    for (int it = 0; it < 32; it++) {
        int idx = it * 256 + tid;
        int r = idx >> 6, ci = idx & 63;
        int grow = m0 + r; if (grow > N - 1) grow = N - 1;
        uint4 val = *(const uint4*)(g_zbf + (size_t)grow * DD + ci * 8);
        *(uint4*)(smem + K8_A + r * 1024 + ((ci ^ (r & 7)) << 4)) = val;
    }

    // ---- warp tiling: mg = warp&3 (m32), jg = warp>>2 (j32 of the 64-chunk) --
    const int mg = warp & 3, jg = warp >> 2;
    const int mbase = mg * 32;
    const uint32_t swa = lane & 7;
    const uint32_t a0base = sbase + K8_A + (uint32_t)(mbase + (lane & 15)) * 1024;
    const int jrow = (lane & 7) + ((lane >> 4) << 3);
    const uint32_t brow_off = (uint32_t)(jg * 32 + jrow) * 512;
    const uint32_t ciBofs = (lane >> 3) & 1;
    const uint32_t ciAofs = lane >> 4;

    float acc[8][4];
#pragma unroll
    for (int t = 0; t < 8; t++)
#pragma unroll
        for (int e = 0; e < 4; e++) acc[t][e] = 0.f;
    float nsq[2][2] = {{0.f, 0.f}, {0.f, 0.f}};
    float cqs[2][2] = {{0.f, 0.f}, {0.f, 0.f}};

    for (int h = 0; h < 16; h++) {
        const int buf = h & 1, kh = h & 1, jc = h >> 1;
        cp_wait1();
        __syncthreads();
        const uint32_t b0base = sbase + K8_B + buf * K8_BHB + brow_off;

#pragma unroll 4
        for (int ktl = 0; ktl < 16; ktl++) {
            uint32_t a0[4], a1[4], b0[4], b1[4];
            uint32_t ciA = (uint32_t)(kh * 16 + ktl) * 2 + ciAofs;
            uint32_t adr = a0base + ((ciA ^ swa) << 4);
            ldmx4(a0, adr);
            ldmx4(a1, adr + 16 * 1024);
            uint32_t ciB = (uint32_t)ktl * 2 + ciBofs;
            uint32_t bdr = b0base + ((ciB ^ swa) << 4);
            ldmx4(b0, bdr);
            ldmx4(b1, bdr + 16 * 512);
            mma16816(acc[0], a0, b0 + 0);
            mma16816(acc[1], a0, b0 + 2);
            mma16816(acc[2], a0, b1 + 0);
            mma16816(acc[3], a0, b1 + 2);
            mma16816(acc[4], a1, b0 + 0);
            mma16816(acc[5], a1, b0 + 2);
            mma16816(acc[6], a1, b1 + 0);
            mma16816(acc[7], a1, b1 + 2);
        }
        __syncthreads();   // all warps done with buf before refill

        if (h & 1) {
            // jc complete: fold (acc + b)^2 and (acc + b)*c, reset acc
#pragma unroll
            for (int mt = 0; mt < 2; mt++)
#pragma unroll
                for (int nt = 0; nt < 4; nt++) {
                    int jglob = jc * 64 + jg * 32 + nt * 8 + (lane & 3) * 2;
                    float bx = sbv[jglob], by = sbv[jglob + 1];
                    float cx = sc[jglob],  cy = sc[jglob + 1];
                    float* a = acc[mt * 4 + nt];
                    float v0 = a[0] + bx, v1 = a[1] + by;
                    float v2 = a[2] + bx, v3 = a[3] + by;
                    nsq[mt][0] += v0 * v0 + v1 * v1;
                    nsq[mt][1] += v2 * v2 + v3 * v3;
                    cqs[mt][0] += v0 * cx + v1 * cy;
                    cqs[mt][1] += v2 * cx + v3 * cy;
                    a[0] = 0.f; a[1] = 0.f; a[2] = 0.f; a[3] = 0.f;
                }
        }
        if (h + 2 < 16) {
            const uint32_t bbuf = sbase + K8_B + buf * K8_BHB;
            const int jc2 = (h + 2) >> 1, kh2 = (h + 2) & 1;
#pragma unroll
            for (int it = 0; it < 8; it++) {
                int idx = it * 256 + tid;
                int j = idx >> 5, ci = idx & 31;
                cp_async16(bbuf + j * 512 + ((ci ^ (j & 7)) << 4),
                           g_wbf + (size_t)(jc2 * 64 + j) * DD + kh2 * 256 + ci * 8);
            }
        }
        cp_commit();
    }

    // ---- merge lane partials: quad lanes share a row ----
#pragma unroll
    for (int mt = 0; mt < 2; mt++)
#pragma unroll
        for (int hh = 0; hh < 2; hh++) {
            float vn = nsq[mt][hh], vc = cqs[mt][hh];
            vn += __shfl_xor_sync(0xffffffffu, vn, 1);
            vn += __shfl_xor_sync(0xffffffffu, vn, 2);
            vc += __shfl_xor_sync(0xffffffffu, vc, 1);
            vc += __shfl_xor_sync(0xffffffffu, vc, 2);
            if ((lane & 3) == 0) {
                int r = mbase + mt * 16 + hh * 8 + (lane >> 2);
                atomicAdd(&snq[r], vn);
                atomicAdd(&sco[r], vc);
            }
        }
    __syncthreads();

    if (tid < 128 && m0 + tid < N) {
        float nx = fmaxf(sqrtf(snq[tid]), EPS);
        out[m0 + tid] = 1.0f - sco[tid] / (nx * g_cnorm);
    }
}

// ================= launch =================
extern "C" void kernel_launch(void* const* d_in, const int* in_sizes, int n_in,
                              void* d_out, int out_size) {
    const float* z = (const float*)d_in[0];
    const float* W = (const float*)d_in[1];
    const float* b = (const float*)d_in[2];
    float* out = (float*)d_out;
    const int N = in_sizes[0] / DD;

    k0_init<<<1024, 256>>>(W);
    k1_pass1<<<1184, 256>>>(z, N);
    k2_c0<<<1, 512>>>(N);
    k3_d2<<<1184, 256>>>(N);
    k45_Zc<<<592, 256>>>(z, N);
    k7_norm<<<1, 512>>>();
    cudaFuncSetAttribute(k8_gemm, cudaFuncAttributeMaxDynamicSharedMemorySize, K8_SMEM);
    k8_gemm<<<(N + 127) / 128, 256, K8_SMEM>>>(b, out, N);
}